// round 17
// baseline (speedup 1.0000x reference)
#include <cuda_runtime.h>
#include <cuda_bf16.h>
#include <math.h>

#define B 16384
#define D 2048
#define E 16
#define C 64

__device__ int g_counts[E];
__device__ int g_bucket[E * B];
__device__ __nv_bfloat16 g_ewhi[E * C * D];   // 4 MB
__device__ __nv_bfloat16 g_ewlo[E * C * D];   // 4 MB

// ======================= helpers ===========================================
__device__ __forceinline__ unsigned smem_u32(const void* p) {
    unsigned a;
    asm("{ .reg .u64 t; cvta.to.shared.u64 t, %1; cvt.u32.u64 %0, t; }" : "=r"(a) : "l"(p));
    return a;
}
// pack two f32 -> bf16x2 (first arg -> low half = element k, second -> high)
__device__ __forceinline__ unsigned pack2(float lo, float hi) {
    unsigned r; asm("cvt.rn.bf16x2.f32 %0, %1, %2;" : "=r"(r) : "f"(hi), "f"(lo)); return r;
}
__device__ __forceinline__ void ldsm4(unsigned addr, unsigned& r0, unsigned& r1, unsigned& r2, unsigned& r3) {
    asm volatile("ldmatrix.sync.aligned.m8n8.x4.shared.b16 {%0,%1,%2,%3}, [%4];"
        : "=r"(r0), "=r"(r1), "=r"(r2), "=r"(r3) : "r"(addr));
}
__device__ __forceinline__ void mma16816(float* c, const unsigned* a, unsigned b0, unsigned b1) {
    asm volatile("mma.sync.aligned.m16n8k16.row.col.f32.bf16.bf16.f32 "
        "{%0,%1,%2,%3}, {%4,%5,%6,%7}, {%8,%9}, {%0,%1,%2,%3};"
        : "+f"(c[0]), "+f"(c[1]), "+f"(c[2]), "+f"(c[3])
        : "r"(a[0]), "r"(a[1]), "r"(a[2]), "r"(a[3]), "r"(b0), "r"(b1));
}
__device__ __forceinline__ void cpasync16(unsigned dst, const void* src, int src_sz) {
    asm volatile("cp.async.cg.shared.global [%0], [%1], 16, %2;"
        :: "r"(dst), "l"(src), "r"(src_sz) : "memory");
}
#define CP_COMMIT() asm volatile("cp.async.commit_group;" ::: "memory")
#define CP_WAIT2()  asm volatile("cp.async.wait_group 2;" ::: "memory")

__device__ __forceinline__ void top2_merge(float& m1, int& c1, float& m2, int& c2,
                                           float om1, int oc1, float om2, int oc2) {
    if (om1 > m1 || (om1 == m1 && oc1 < c1)) {
        float nm2; int nc2;
        if (m1 > om2 || (m1 == om2 && c1 < oc2)) { nm2 = m1; nc2 = c1; }
        else { nm2 = om2; nc2 = oc2; }
        m1 = om1; c1 = oc1; m2 = nm2; c2 = nc2;
    } else if (om1 > m2 || (om1 == m2 && oc1 < c2)) {
        m2 = om1; c2 = oc1;
    }
}

// ======================= Kernel 0: prep (zero counts + convert W) ==========
__global__ __launch_bounds__(256) void prep_kernel(const float* __restrict__ ew) {
    if (blockIdx.x == 0 && threadIdx.x < E) g_counts[threadIdx.x] = 0;
    int idx = (blockIdx.x * 256 + threadIdx.x) * 8;   // grid 1024 covers 2,097,152
    if (idx < E * C * D) {
        float4 v0 = *(const float4*)(ew + idx);
        float4 v1 = *(const float4*)(ew + idx + 4);
        float f[8] = {v0.x, v0.y, v0.z, v0.w, v1.x, v1.y, v1.z, v1.w};
        unsigned h[4], l[4];
        #pragma unroll
        for (int i = 0; i < 4; i++) {
            unsigned hp = pack2(f[2*i], f[2*i+1]);
            float h0 = __uint_as_float(hp << 16);
            float h1 = __uint_as_float(hp & 0xFFFF0000u);
            h[i] = hp;
            l[i] = pack2(f[2*i] - h0, f[2*i+1] - h1);
        }
        *(uint4*)(g_ewhi + idx) = make_uint4(h[0], h[1], h[2], h[3]);
        *(uint4*)(g_ewlo + idx) = make_uint4(l[0], l[1], l[2], l[3]);
    }
}

// ======================= Kernel 1: coarse router (fp32, proven) ============
#define TK 32
#define NCH (D / TK)
__device__ __forceinline__ int idx64(int kr, int col) {
    return kr * 64 + (((col >> 2) ^ ((kr >> 2) & 7)) << 2) + (col & 3);
}
__device__ __forceinline__ int idx64v(int kr, int c4) { return kr * 64 + (((c4) ^ ((kr >> 2) & 7)) << 2); }
__device__ __forceinline__ int idx16(int kr, int col) {
    return kr * 16 + (((col >> 2) ^ ((kr >> 2) & 3)) << 2) + (col & 3);
}

__global__ __launch_bounds__(256) void coarse_kernel(
    const float* __restrict__ features, const float* __restrict__ cw,
    const float* __restrict__ cb, float* __restrict__ out_coarse, float* __restrict__ out_eid)
{
    __shared__ __align__(16) float fsb[2 * TK * 64];
    __shared__ __align__(16) float wsb[2 * TK * 16];

    int tid = threadIdx.x;
    int s0 = blockIdx.x * 64;
    int ty = tid >> 4, tx = tid & 15;
    int st_r = tid >> 3, st_kc = tid & 7;
    int w_e = tid >> 3, w_kc = tid & 7;

    float4 pf[2], pw;
    float acc[4] = {0.f, 0.f, 0.f, 0.f};

    pf[0] = *(const float4*)(features + (size_t)(s0 + st_r) * D + st_kc * 4);
    pf[1] = *(const float4*)(features + (size_t)(s0 + st_r + 32) * D + st_kc * 4);
    if (tid < 128) pw = *(const float4*)(cw + (size_t)w_e * D + w_kc * 4);

    #pragma unroll
    for (int it = 0; it < 2; it++) {
        int s = st_r + it * 32;
        float v[4] = {pf[it].x, pf[it].y, pf[it].z, pf[it].w};
        #pragma unroll
        for (int j = 0; j < 4; j++) fsb[idx64(st_kc * 4 + j, s)] = v[j];
    }
    if (tid < 128) {
        float v[4] = {pw.x, pw.y, pw.z, pw.w};
        #pragma unroll
        for (int j = 0; j < 4; j++) wsb[idx16(w_kc * 4 + j, w_e)] = v[j];
    }
    __syncthreads();

    for (int chunk = 0; chunk < NCH; chunk++) {
        int cur = chunk & 1, nxt = cur ^ 1;
        if (chunk + 1 < NCH) {
            int k0 = (chunk + 1) * TK;
            pf[0] = *(const float4*)(features + (size_t)(s0 + st_r) * D + k0 + st_kc * 4);
            pf[1] = *(const float4*)(features + (size_t)(s0 + st_r + 32) * D + k0 + st_kc * 4);
            if (tid < 128) pw = *(const float4*)(cw + (size_t)w_e * D + k0 + w_kc * 4);
        }
        const float* fsc = fsb + cur * (TK * 64);
        const float* wsc = wsb + cur * (TK * 16);
        #pragma unroll
        for (int kk = 0; kk < TK; kk++) {
            float4 fa = *(const float4*)&fsc[idx64v(kk, ty)];
            float w = wsc[idx16(kk, tx)];
            acc[0] = fmaf(fa.x, w, acc[0]);
            acc[1] = fmaf(fa.y, w, acc[1]);
            acc[2] = fmaf(fa.z, w, acc[2]);
            acc[3] = fmaf(fa.w, w, acc[3]);
        }
        if (chunk + 1 < NCH) {
            #pragma unroll
            for (int it = 0; it < 2; it++) {
                int s = st_r + it * 32;
                float v[4] = {pf[it].x, pf[it].y, pf[it].z, pf[it].w};
                #pragma unroll
                for (int j = 0; j < 4; j++) fsb[nxt * (TK * 64) + idx64(st_kc * 4 + j, s)] = v[j];
            }
            if (tid < 128) {
                float v[4] = {pw.x, pw.y, pw.z, pw.w};
                #pragma unroll
                for (int j = 0; j < 4; j++) wsb[nxt * (TK * 16) + idx16(w_kc * 4 + j, w_e)] = v[j];
            }
            __syncthreads();
        }
    }

    float bias = cb[tx];
    #pragma unroll
    for (int i = 0; i < 4; i++) {
        float v = acc[i] + bias;
        int gs = s0 + ty * 4 + i;
        out_coarse[(size_t)gs * E + tx] = v;
        float mv = v; int mi = tx;
        #pragma unroll
        for (int off = 1; off < 16; off <<= 1) {
            float ov = __shfl_xor_sync(0xffffffffu, mv, off);
            int   oi = __shfl_xor_sync(0xffffffffu, mi, off);
            if (ov > mv || (ov == mv && oi < mi)) { mv = ov; mi = oi; }
        }
        if (tx == 0) {
            out_eid[gs] = (float)mi;
            int pos = atomicAdd(&g_counts[mi], 1);
            g_bucket[mi * B + pos] = gs;
        }
    }
}

// ======================= Kernel 2: expert GEMM, cp.async 4-stage ===========
// Tile M=64 x N=64, 128 threads (4 warps). A staged f32 (pitch 160B),
// W staged bf16 hi/lo (pre-converted, pitch 80B). A-frags built from f32
// smem (hi/lo split in regs); W-frags via ldmatrix (R13-proven layout).
#define APITCH 160                // 32 f32 + pad, conflict-free LDS.64
#define WPITCH 80
#define STG_A  0
#define STG_WH 10240
#define STG_WL 15360
#define STG_SZ 20480
#define NSTAGE 4
#define OFF_RIDX (NSTAGE * STG_SZ)            // 81920
#define OFF_BIAS (OFF_RIDX + 256)
#define SMEM_TC  (OFF_BIAS + 256)             // 82432
#define NCHT (D / 32)             // 64
#define MT_MAX 32

__global__ void __launch_bounds__(128, 2) expert_mma_kernel(
    const float* __restrict__ features, const float* __restrict__ ew,
    const float* __restrict__ eb, float* __restrict__ out_local,
    float* __restrict__ out_global)
{
    extern __shared__ __align__(16) char dsm[];
    int e = blockIdx.x, mt = blockIdx.y;
    int cnt = g_counts[e];
    int m0 = mt * 64;
    if (m0 >= cnt) return;

    unsigned sb = smem_u32(dsm);
    int tid = threadIdx.x, wid = tid >> 5, lid = tid & 31;

    if (tid < 64) {
        int r = m0 + tid;
        ((int*)(dsm + OFF_RIDX))[tid] = (r < cnt) ? g_bucket[e * B + r] : -1;
        ((float*)(dsm + OFF_BIAS))[tid] = eb[e * C + tid];
    }
    __syncthreads();

    const int* ridx = (const int*)(dsm + OFF_RIDX);
    const float* bias = (const float*)(dsm + OFF_BIAS);
    const float* wbase = ew + (size_t)e * C * D;
    const __nv_bfloat16* whB = g_ewhi + (size_t)e * C * D;
    const __nv_bfloat16* wlB = g_ewlo + (size_t)e * C * D;

    // A staging: 512 x 16B tasks (4/thread): row = task>>3, col16 = task&7
    int a_row[4], a_c16[4];
    const float* a_src[4];
    int a_sz[4];
    #pragma unroll
    for (int i = 0; i < 4; i++) {
        int task = tid + i * 128;
        a_row[i] = task >> 3;
        a_c16[i] = task & 7;
        int fr = ridx[a_row[i]];
        a_src[i] = (fr >= 0) ? (features + (size_t)fr * D + a_c16[i] * 4) : features;
        a_sz[i]  = (fr >= 0) ? 16 : 0;
    }
    // W staging: 256 x 16B tasks per matrix (2/thread): row = task>>2, g16 = task&3
    int w_row[2], w_g16[2];
    #pragma unroll
    for (int i = 0; i < 2; i++) {
        int task = tid + i * 128;
        w_row[i] = task >> 2;
        w_g16[i] = task & 3;
    }

    // issue one chunk's cp.asyncs into stage buffer
    auto issue = [&](int ch) {
        unsigned base = sb + (unsigned)((ch & 3) * STG_SZ);
        int k0 = ch * 32;
        #pragma unroll
        for (int i = 0; i < 4; i++)
            cpasync16(base + STG_A + (unsigned)(a_row[i] * APITCH + a_c16[i] * 16),
                      a_src[i] + k0, a_sz[i]);
        #pragma unroll
        for (int i = 0; i < 2; i++) {
            unsigned wo = (unsigned)(w_row[i] * WPITCH + w_g16[i] * 16);
            const __nv_bfloat16* wsrc = whB + (size_t)w_row[i] * D + k0 + w_g16[i] * 8;
            const __nv_bfloat16* lsrc = wlB + (size_t)w_row[i] * D + k0 + w_g16[i] * 8;
            cpasync16(base + STG_WH + wo, wsrc, 16);
            cpasync16(base + STG_WL + wo, lsrc, 16);
        }
        CP_COMMIT();
    };

    float c[8][4];
    #pragma unroll
    for (int nb = 0; nb < 8; nb++)
        #pragma unroll
        for (int j = 0; j < 4; j++) c[nb][j] = 0.f;

    // prologue: stages 0..2
    issue(0); issue(1); issue(2);

    int g  = lid >> 2;            // fragment row within strip
    int tg = lid & 3;             // k-pair index
    int wrow = wid * 16;
    unsigned boffl = (unsigned)((((lid >> 4) * 8 + (lid & 7)) * WPITCH) + (((lid >> 3) & 1) * 16));

    #pragma unroll 1
    for (int ch = 0; ch < NCHT; ch++) {
        CP_WAIT2();
        __syncthreads();
        if (ch + 3 < NCHT) issue(ch + 3); else CP_COMMIT();

        unsigned base = sb + (unsigned)((ch & 3) * STG_SZ);
        const float* Af = (const float*)(dsm + (ch & 3) * STG_SZ);

        #pragma unroll
        for (int s = 0; s < 2; s++) {
            // build A hi/lo fragments from f32 smem
            unsigned ahi[4], alo[4];
            #pragma unroll
            for (int q = 0; q < 4; q++) {
                int row = wrow + g + ((q & 1) ? 8 : 0);
                int col = s * 16 + ((q >> 1) ? 8 : 0) + tg * 2;
                float2 f = *(const float2*)(Af + row * (APITCH / 4) + col);
                unsigned hp = pack2(f.x, f.y);
                float h0 = __uint_as_float(hp << 16);
                float h1 = __uint_as_float(hp & 0xFFFF0000u);
                ahi[q] = hp;
                alo[q] = pack2(f.x - h0, f.y - h1);
            }
            #pragma unroll
            for (int nbp = 0; nbp < 4; nbp++) {
                unsigned bh[4], bl[4];
                unsigned bo = boffl + (unsigned)(nbp * 16 * WPITCH) + s * 32;
                ldsm4(base + STG_WH + bo, bh[0], bh[1], bh[2], bh[3]);
                ldsm4(base + STG_WL + bo, bl[0], bl[1], bl[2], bl[3]);
                mma16816(c[2*nbp],     ahi, bh[0], bh[1]);
                mma16816(c[2*nbp],     ahi, bl[0], bl[1]);
                mma16816(c[2*nbp],     alo, bh[0], bh[1]);
                mma16816(c[2*nbp + 1], ahi, bh[2], bh[3]);
                mma16816(c[2*nbp + 1], ahi, bl[2], bl[3]);
                mma16816(c[2*nbp + 1], alo, bh[2], bh[3]);
            }
        }
    }

    // ---- epilogue (R13/R15-proven) ----
    int qm = lid & 3, rb = lid >> 2;
    #pragma unroll
    for (int nb = 0; nb < 8; nb++) {
        float b0 = bias[nb * 8 + 2 * qm];
        float b1 = bias[nb * 8 + 2 * qm + 1];
        c[nb][0] += b0; c[nb][1] += b1;
        c[nb][2] += b0; c[nb][3] += b1;
    }

    #pragma unroll
    for (int half = 0; half < 2; half++) {
        int row  = wid * 16 + rb + half * 8;
        int frow = ridx[row];
        int j0 = half * 2;

        float m1 = -3.4e38f, m2 = -3.4e38f; int c1 = 0, c2 = 0;
        #pragma unroll
        for (int nb = 0; nb < 8; nb++) {
            #pragma unroll
            for (int j = 0; j < 2; j++) {
                float v = c[nb][j0 + j];
                int col = nb * 8 + 2 * qm + j;
                if (v > m1 || (v == m1 && col < c1)) { m2 = m1; c2 = c1; m1 = v; c1 = col; }
                else if (v > m2 || (v == m2 && col < c2)) { m2 = v; c2 = col; }
            }
        }
        #pragma unroll
        for (int off = 1; off < 4; off <<= 1) {
            float om1 = __shfl_xor_sync(0xffffffffu, m1, off);
            int   oc1 = __shfl_xor_sync(0xffffffffu, c1, off);
            float om2 = __shfl_xor_sync(0xffffffffu, m2, off);
            int   oc2 = __shfl_xor_sync(0xffffffffu, c2, off);
            top2_merge(m1, c1, m2, c2, om1, oc1, om2, oc2);
        }

        int win = c1;
        if (frow >= 0 && (m1 - m2) < 2e-4f) {
            const float* fr = features + (size_t)frow * D;
            const float* w1 = wbase + (size_t)c1 * D;
            const float* w2 = wbase + (size_t)c2 * D;
            float s1 = 0.f, s2 = 0.f;
            for (int k = qm * 4; k < D; k += 16) {
                float4 f = *(const float4*)(fr + k);
                float4 a = *(const float4*)(w1 + k);
                float4 b = *(const float4*)(w2 + k);
                s1 = fmaf(f.x, a.x, fmaf(f.y, a.y, fmaf(f.z, a.z, fmaf(f.w, a.w, s1))));
                s2 = fmaf(f.x, b.x, fmaf(f.y, b.y, fmaf(f.z, b.z, fmaf(f.w, b.w, s2))));
            }
            #pragma unroll
            for (int off = 1; off < 4; off <<= 1) {
                s1 += __shfl_xor_sync(0xffffffffu, s1, off);
                s2 += __shfl_xor_sync(0xffffffffu, s2, off);
            }
            s1 += bias[c1]; s2 += bias[c2];
            if (s2 > s1 || (s2 == s1 && c2 < c1)) win = c2;
        }

        float sum = 0.f;
        float ev[16];
        #pragma unroll
        for (int nb = 0; nb < 8; nb++) {
            #pragma unroll
            for (int j = 0; j < 2; j++) {
                float v = expf(c[nb][j0 + j] - m1);
                ev[nb * 2 + j] = v;
                sum += v;
            }
        }
        #pragma unroll
        for (int off = 1; off < 4; off <<= 1)
            sum += __shfl_xor_sync(0xffffffffu, sum, off);
        float inv = 1.0f / sum;

        if (frow >= 0) {
            float* dst = out_local + (size_t)frow * C;
            #pragma unroll
            for (int nb = 0; nb < 8; nb++) {
                float2 o = make_float2(ev[nb * 2] * inv, ev[nb * 2 + 1] * inv);
                *(float2*)(dst + nb * 8 + 2 * qm) = o;
            }
            if (qm == 0)
                out_global[frow] = (float)(win + e * C);
        }
    }
}

// ===========================================================================
// Output layout: coarse [B*E] | expert_id [B] | local_preds [B*C] | global [B]
// ===========================================================================
extern "C" void kernel_launch(void* const* d_in, const int* in_sizes, int n_in,
                              void* d_out, int out_size) {
    const float* features = (const float*)d_in[0];
    const float* cw       = (const float*)d_in[1];
    const float* cb       = (const float*)d_in[2];
    const float* ew       = (const float*)d_in[3];
    const float* eb       = (const float*)d_in[4];

    float* out        = (float*)d_out;
    float* out_coarse = out;
    float* out_eid    = out + (size_t)B * E;
    float* out_local  = out_eid + B;
    float* out_global = out_local + (size_t)B * C;

    static int attr_set = 0;
    if (!attr_set) {
        cudaFuncSetAttribute(expert_mma_kernel, cudaFuncAttributeMaxDynamicSharedMemorySize, SMEM_TC);
        attr_set = 1;
    }

    prep_kernel<<<1024, 256>>>(ew);
    coarse_kernel<<<B / 64, 256>>>(features, cw, cb, out_coarse, out_eid);
    dim3 g2(E, MT_MAX);   // covers cnt_e <= 2048 (mean 1024)
    expert_mma_kernel<<<g2, 128, SMEM_TC>>>(features, ew, eb, out_local, out_global);
}